// round 6
// baseline (speedup 1.0000x reference)
#include <cuda_runtime.h>
#include <cstdint>

#define B_DIM   2048
#define IN_DIM  4096
#define OUT_DIM 4096
#define FAN     64

#define BT        8          // batch rows per block tile
#define ROWSTRIDE 4100       // words; 4100 % 32 == 4 -> bank = idx + 4*b
#define THREADS   1024       // 32 warps
#define OSPLIT    2
#define OCHUNK    (OUT_DIM / OSPLIT)   // 2048 outputs per block
#define OPP       128                  // 32 warps * 4 outputs per pass
#define NPASS     (OCHUNK / OPP)       // 16

// (weight<<32 | idx) pairs, class-sorted + rotated per output (see prep_kernel)
__device__ unsigned long long g_pack[OUT_DIM * FAN];

// ---------------------------------------------------------------------------
// Prep: pack (idx,w) into u64, counting-sort each output's 64 entries by
// idx&3 (smem bank class under ROWSTRIDE=4100), rotate member (o&3) by 16 so
// the 4 outputs sharing a warp hit distinct bank classes at each step.
// Pure permutation of the summation order -> numerically identical (fp32).
//
// Robust mask dtype handling: the reference requests int64 but JAX default
// config (x64 disabled) materializes int32. Detect on-device: for int64
// values < 4096, all odd 32-bit words are zero; for int32 random indices
// that is (1/4096)^8-improbable. Then flat index is (pos << is64).
// ---------------------------------------------------------------------------
__global__ void prep_kernel(const float* __restrict__ w,
                            const unsigned* __restrict__ m32) {
    int o = blockIdx.x * blockDim.x + threadIdx.x;
    if (o >= OUT_DIM) return;

    // dtype sniff (uniform across threads; L1-broadcast)
    unsigned odd_or = 0;
    #pragma unroll
    for (int i = 1; i < 16; i += 2) odd_or |= m32[i];
    const unsigned sh = (odd_or == 0u) ? 1u : 0u;   // 1 -> int64, 0 -> int32

    const size_t base = (size_t)o * FAN;
    const float* wrow = w + base;

    int cnt0 = 0, cnt1 = 0, cnt2 = 0, cnt3 = 0;
    #pragma unroll 4
    for (int f = 0; f < FAN; f++) {
        unsigned c = m32[(base + f) << sh] & 3u;
        cnt0 += (c == 0); cnt1 += (c == 1); cnt2 += (c == 2); cnt3 += (c == 3);
    }
    int start[4];
    start[0] = 0;
    start[1] = cnt0;
    start[2] = cnt0 + cnt1;
    start[3] = cnt0 + cnt1 + cnt2;

    const int rot = (o & 3) * 16;
    #pragma unroll 4
    for (int f = 0; f < FAN; f++) {
        unsigned idx = m32[(base + f) << sh];
        unsigned wb  = __float_as_uint(wrow[f]);
        int p = start[idx & 3]++;
        int slot = (p - rot) & 63;     // compute reads slot t -> sorted pos (t+rot)&63
        g_pack[base + slot] = ((unsigned long long)wb << 32) | idx;
    }
}

// ---------------------------------------------------------------------------
// Main gather kernel.
//   smem tile: 8 batch rows, row stride 4100 words  (bank = idx + 4*b)
//   warp = 4 output-groups (lane>>3) x 8 batch lanes (lane&7)
//   each f-step: group-broadcast LDG.128 of packed (idx,w), conflict-scheduled
//   LDS gather, fp32 FMA. One barrier per block, none in the pass loop.
// ---------------------------------------------------------------------------
__global__ __launch_bounds__(THREADS, 1)
void gather_kernel(const float* __restrict__ input,
                   const float* __restrict__ bias,
                   float* __restrict__ out) {
    extern __shared__ float tile[];    // BT * ROWSTRIDE floats = 131200 B

    const int tid   = threadIdx.x;
    const int wid   = tid >> 5;
    const int lane  = tid & 31;
    const int brow0 = blockIdx.x * BT;
    const int obase = blockIdx.y * OCHUNK;

    // ---- load 8 input rows into smem (4 warps per row, float4, conflict-free)
    {
        int r = wid >> 2;
        const float4* src = (const float4*)(input + (size_t)(brow0 + r) * IN_DIM);
        float* dst = tile + r * ROWSTRIDE;   // row start byte offset % 16 == 0
        #pragma unroll
        for (int j = (wid & 3) * 32 + lane; j < IN_DIM / 4; j += 128) {
            float4 v = src[j];
            *(float4*)(dst + 4 * j) = v;
        }
    }
    __syncthreads();

    const int g  = lane >> 3;          // output group within warp (== o & 3)
    const int bb = lane & 7;           // batch lane
    const float* srow  = tile + bb * ROWSTRIDE;
    const int olocal   = (wid << 2) + g;

    for (int pass = 0; pass < NPASS; pass++) {
        const int o = obase + pass * OPP + olocal;
        const ulonglong2* pk = (const ulonglong2*)(g_pack + (size_t)o * FAN);

        float acc0 = 0.f, acc1 = 0.f;
        #pragma unroll 8
        for (int f2 = 0; f2 < FAN / 2; f2++) {
            ulonglong2 v = pk[f2];                 // 16B, broadcast across 8 lanes
            unsigned ia = (unsigned)v.x;
            float    wa = __uint_as_float((unsigned)(v.x >> 32));
            unsigned ib = (unsigned)v.y;
            float    wb = __uint_as_float((unsigned)(v.y >> 32));
            acc0 = fmaf(srow[ia], wa, acc0);
            acc1 = fmaf(srow[ib], wb, acc1);
        }
        out[(size_t)(brow0 + bb) * OUT_DIM + o] = acc0 + acc1 + bias[o];
    }
}

// ---------------------------------------------------------------------------
// Harness entry. Inputs (metadata order):
//   0: input            float32 [2048, 4096]
//   1: condensed_weight float32 [4096, 64]
//   2: bias             float32 [4096]
//   3: input_mask       int64-or-int32 [4096, 64]  (detected on device)
// Output: float32 [2048, 4096]
// ---------------------------------------------------------------------------
extern "C" void kernel_launch(void* const* d_in, const int* in_sizes, int n_in,
                              void* d_out, int out_size) {
    const float*    input  = (const float*)d_in[0];
    const float*    weight = (const float*)d_in[1];
    const float*    bias   = (const float*)d_in[2];
    const unsigned* mask32 = (const unsigned*)d_in[3];
    float*          out    = (float*)d_out;
    (void)in_sizes; (void)n_in; (void)out_size;

    prep_kernel<<<OUT_DIM / 128, 128>>>(weight, mask32);

    const int smem_bytes = BT * ROWSTRIDE * (int)sizeof(float);   // 131200
    cudaFuncSetAttribute(gather_kernel,
                         cudaFuncAttributeMaxDynamicSharedMemorySize, smem_bytes);

    dim3 grid(B_DIM / BT, OSPLIT);
    gather_kernel<<<grid, THREADS, smem_bytes>>>(input, bias, out);
}